// round 11
// baseline (speedup 1.0000x reference)
#include <cuda_runtime.h>
#include <cuda_fp16.h>
#include <cstdint>

// ---------------- problem constants ----------------
static constexpr int TOKENS = 4096;
static constexpr int IN_F   = 4096;
static constexpr int OUT_F  = 11008;

static constexpr int BM = 128;
static constexpr int BN = 128;
static constexpr int BK = 64;          // 64 fp16 = 128 bytes per row (SW128 atom row)
static constexpr int STAGES = 3;

static constexpr int M_TILES = TOKENS / BM;   // 32
static constexpr int N_TILES = OUT_F / BN;    // 86
static constexpr int K_TILES = IN_F / BK;     // 64

static constexpr int TILE_BYTES = 128 * BK * 2;     // 16384 (A tile == B tile)
static constexpr int STAGE_BYTES = 2 * TILE_BYTES;  // 32768
static constexpr int SMEM_BYTES = STAGES * STAGE_BYTES; // 98304

static constexpr int X_BLOCKS = M_TILES * K_TILES;  // 2048
static constexpr int W_BLOCKS = N_TILES * K_TILES;  // 5504

// ---------------- device scratch (no cudaMalloc allowed) ----------------
__device__ __align__(1024) uint8_t g_xbuf[(size_t)M_TILES * K_TILES * TILE_BYTES]; // 32 MB fp16 tiles, SW128
__device__ __align__(1024) uint8_t g_wbuf[(size_t)N_TILES * K_TILES * TILE_BYTES]; // 88 MB fp16 tiles, SW128

// ---------------- helpers ----------------
__device__ __forceinline__ uint32_t smem_u32(const void* p) {
    uint32_t a;
    asm("{ .reg .u64 t; cvta.to.shared.u64 t, %1; cvt.u32.u64 %0, t; }" : "=r"(a) : "l"(p));
    return a;
}
__device__ __forceinline__ uint32_t h2u(__half2 h) { uint32_t u; __builtin_memcpy(&u, &h, 4); return u; }
__device__ __forceinline__ uint32_t swz(uint32_t off) { return off ^ ((off >> 3) & 0x70); }

__device__ __forceinline__ void cpasync16(uint32_t dst, const void* src) {
    asm volatile("cp.async.cg.shared.global [%0], [%1], 16;" :: "r"(dst), "l"(src));
}
__device__ __forceinline__ void cp_commit() { asm volatile("cp.async.commit_group;" ::: "memory"); }
__device__ __forceinline__ void cp_wait1()  { asm volatile("cp.async.wait_group 1;" ::: "memory"); }

__device__ __forceinline__ void ldsm4(uint32_t* r, uint32_t addr) {
    asm volatile("ldmatrix.sync.aligned.m8n8.x4.shared.b16 {%0,%1,%2,%3}, [%4];"
                 : "=r"(r[0]), "=r"(r[1]), "=r"(r[2]), "=r"(r[3]) : "r"(addr) : "memory");
}
__device__ __forceinline__ void mma16816(float* c, const uint32_t* a, const uint32_t* b) {
    asm volatile(
        "mma.sync.aligned.m16n8k16.row.col.f32.f16.f16.f32 "
        "{%0,%1,%2,%3}, {%4,%5,%6,%7}, {%8,%9}, {%0,%1,%2,%3};"
        : "+f"(c[0]), "+f"(c[1]), "+f"(c[2]), "+f"(c[3])
        : "r"(a[0]), "r"(a[1]), "r"(a[2]), "r"(a[3]), "r"(b[0]), "r"(b[1]));
}

// ---------------- merged prep kernel ----------------
// blocks [0, X_BLOCKS):          x fp32 -> fp16, tiled + SW128
// blocks [X_BLOCKS, +W_BLOCKS):  packed nibbles (int32 per byte) -> fp16 dequant W, tiled + SW128
__global__ void prep_kernel(const float* __restrict__ x,
                            const int* __restrict__ wp,
                            const float* __restrict__ scale,
                            const float* __restrict__ zero) {
    const int blk = blockIdx.x;
    const int r = threadIdx.x; // 0..127 = row within tile
    if (blk < X_BLOCKS) {
        const int mt = blk / K_TILES;
        const int kt = blk % K_TILES;
        const float4* src = (const float4*)(x + (size_t)(mt * BM + r) * IN_F + kt * BK);
        uint8_t* dst = g_xbuf + (size_t)blk * TILE_BYTES;
#pragma unroll
        for (int g = 0; g < 8; g++) {
            float4 a = src[2 * g];
            float4 b = src[2 * g + 1];
            uint4 v;
            v.x = h2u(__floats2half2_rn(a.x, a.y));
            v.y = h2u(__floats2half2_rn(a.z, a.w));
            v.z = h2u(__floats2half2_rn(b.x, b.y));
            v.w = h2u(__floats2half2_rn(b.z, b.w));
            uint32_t off = (uint32_t)(r * 128 + g * 16);
            *(uint4*)(dst + swz(off)) = v;
        }
    } else {
        const int wblk = blk - X_BLOCKS;
        const int nt = wblk / K_TILES;
        const int kt = wblk % K_TILES;
        const int row = nt * BN + r;
        const float s = scale[row];
        const float b = -zero[row] * s;
        const uint4* src = (const uint4*)(wp + (size_t)row * (IN_F / 2) + kt * (BK / 2)); // 32 ints
        uint8_t* dst = g_wbuf + (size_t)wblk * TILE_BYTES;
#pragma unroll
        for (int j = 0; j < 8; j++) {
            uint4 q = src[j];
            uint32_t e[4] = {q.x, q.y, q.z, q.w};
            uint32_t h[4];
#pragma unroll
            for (int t = 0; t < 4; t++) {
                float v0 = fmaf((float)(e[t] & 15u), s, b);          // even k
                float v1 = fmaf((float)((e[t] >> 4) & 15u), s, b);   // odd k
                h[t] = h2u(__floats2half2_rn(v0, v1));
            }
            uint4 v = make_uint4(h[0], h[1], h[2], h[3]);
            uint32_t off = (uint32_t)(r * 128 + j * 16);
            *(uint4*)(dst + swz(off)) = v;
        }
    }
}

// ---------------- main GEMM: mma.sync (HMMA) + cp.async 3-stage pipeline ----------------
// 256 threads = 8 warps in a 4(M) x 2(N) grid; warp tile 32x64.
// Both A and B ldmatrix loads are software-pipelined (parity buffers).
__global__ void __launch_bounds__(256, 2) gemm_kernel(float* __restrict__ out) {
    extern __shared__ __align__(1024) uint8_t sm[];
    uint32_t sb = smem_u32(sm);
    const int tid  = threadIdx.x;
    const int lane = tid & 31;
    const int warp = tid >> 5;
    const int warp_m = warp & 3;
    const int warp_n = warp >> 2;
    const int mt = blockIdx.x % M_TILES;
    const int nt = blockIdx.x / M_TILES;

    const uint8_t* ag = g_xbuf + (size_t)(mt * K_TILES) * TILE_BYTES;
    const uint8_t* bg = g_wbuf + (size_t)(nt * K_TILES) * TILE_BYTES;

    const uint32_t cp_off = (uint32_t)tid * 64;

    // prologue: stages 0 and 1
#pragma unroll
    for (int s = 0; s < 2; s++) {
        uint32_t dA = sb + s * STAGE_BYTES + cp_off;
        uint32_t dB = dA + TILE_BYTES;
        const uint8_t* srcA = ag + (size_t)s * TILE_BYTES + cp_off;
        const uint8_t* srcB = bg + (size_t)s * TILE_BYTES + cp_off;
#pragma unroll
        for (int j = 0; j < 4; j++) {
            cpasync16(dA + j * 16, srcA + j * 16);
            cpasync16(dB + j * 16, srcB + j * 16);
        }
        cp_commit();
    }

    // per-lane ldmatrix address components (SW128: swz(r*128+c) = r*128 + (c ^ ((r&7)<<4)))
    const int a_row = warp_m * 32 + (lane & 15);          // + 16*mtile
    const uint32_t a_xor = (uint32_t)((a_row & 7) << 4);
    const uint32_t a_cb  = (uint32_t)((lane >> 4) << 4);  // 0 or 16
    const int b_row = warp_n * 64 + (lane & 7) + ((lane >> 4) << 3);  // + 16*p
    const uint32_t b_xor = (uint32_t)((b_row & 7) << 4);
    const uint32_t b_cb  = (uint32_t)((lane & 8) << 1);   // 0 or 16

    const uint32_t aoff0 = (uint32_t)(a_row +  0) * 128;
    const uint32_t aoff1 = (uint32_t)(a_row + 16) * 128;

    float acc[2][8][4];
#pragma unroll
    for (int i = 0; i < 2; i++)
#pragma unroll
        for (int j = 0; j < 8; j++)
#pragma unroll
            for (int q = 0; q < 4; q++) acc[i][j][q] = 0.f;

    // fragment parity buffers
    uint32_t afrag[2][2][4];  // [k16 parity][mtile][regs]
    uint32_t bfrag[2][4];     // [step parity][regs]

#pragma unroll 1
    for (int kt = 0; kt < K_TILES; kt++) {
        cp_wait1();
        __syncthreads();

        // issue stage kt+2
        if (kt + 2 < K_TILES) {
            int s = (kt + 2) % STAGES;
            uint32_t dA = sb + s * STAGE_BYTES + cp_off;
            uint32_t dB = dA + TILE_BYTES;
            const uint8_t* srcA = ag + (size_t)(kt + 2) * TILE_BYTES + cp_off;
            const uint8_t* srcB = bg + (size_t)(kt + 2) * TILE_BYTES + cp_off;
#pragma unroll
            for (int j = 0; j < 4; j++) {
                cpasync16(dA + j * 16, srcA + j * 16);
                cpasync16(dB + j * 16, srcB + j * 16);
            }
        }
        cp_commit();

        // compute stage kt — fully software-pipelined fragment loads
        uint32_t sA = sb + (kt % STAGES) * STAGE_BYTES;
        uint32_t sB = sA + TILE_BYTES;

        // prime: A for k16=0, B for step 0 (k16=0, p=0)
        {
            uint32_t kc0 = a_cb ^ a_xor;
            ldsm4(afrag[0][0], sA + aoff0 + kc0);
            ldsm4(afrag[0][1], sA + aoff1 + kc0);
            uint32_t baddr = sB + (uint32_t)(b_row) * 128 + (b_cb ^ b_xor);
            ldsm4(bfrag[0], baddr);
        }

#pragma unroll
        for (int step = 0; step < 16; step++) {
            const int k16 = step >> 2;
            const int p   = step & 3;
            // prefetch A for k16+1 at the start of each k16 group
            if (p == 0 && k16 < 3) {
                uint32_t kn = ((uint32_t)((k16 + 1) * 32) + a_cb) ^ a_xor;
                ldsm4(afrag[(k16 + 1) & 1][0], sA + aoff0 + kn);
                ldsm4(afrag[(k16 + 1) & 1][1], sA + aoff1 + kn);
            }
            // prefetch B for step+1
            if (step < 15) {
                const int k16n = (step + 1) >> 2;
                const int pn   = (step + 1) & 3;
                uint32_t kcn = (uint32_t)(k16n * 32);
                uint32_t baddr = sB + (uint32_t)(b_row + 16 * pn) * 128 + ((kcn + b_cb) ^ b_xor);
                ldsm4(bfrag[(step + 1) & 1], baddr);
            }
            // mma quad for (k16, p)
            const uint32_t* a0 = afrag[k16 & 1][0];
            const uint32_t* a1 = afrag[k16 & 1][1];
            const uint32_t* bb = bfrag[step & 1];
            mma16816(acc[0][2 * p + 0], a0, bb + 0);
            mma16816(acc[0][2 * p + 1], a0, bb + 2);
            mma16816(acc[1][2 * p + 0], a1, bb + 0);
            mma16816(acc[1][2 * p + 1], a1, bb + 2);
        }
    }

    // epilogue: plain accumulator stores (scale/zero already folded into W)
    const int m_lo = mt * BM + warp_m * 32 + (lane >> 2);
    const int n_lo = nt * BN + warp_n * 64 + 2 * (lane & 3);
#pragma unroll
    for (int mtile = 0; mtile < 2; mtile++) {
        int m0 = m_lo + 16 * mtile;
        float* o0 = out + (size_t)m0 * OUT_F + n_lo;
        float* o1 = o0 + (size_t)8 * OUT_F;
#pragma unroll
        for (int p = 0; p < 8; p++) {
            float2 v0, v1;
            v0.x = acc[mtile][p][0];
            v0.y = acc[mtile][p][1];
            v1.x = acc[mtile][p][2];
            v1.y = acc[mtile][p][3];
            *(float2*)(o0 + 8 * p) = v0;
            *(float2*)(o1 + 8 * p) = v1;
        }
    }
}

// ---------------- launch ----------------
extern "C" void kernel_launch(void* const* d_in, const int* in_sizes, int n_in,
                              void* d_out, int out_size) {
    const float* x     = (const float*)d_in[0];
    const int*   wpack = (const int*)d_in[1];   // uint8 promoted to int32 by harness
    const float* scale = (const float*)d_in[2];
    const float* zero  = (const float*)d_in[3];
    float*       out   = (float*)d_out;

    cudaFuncSetAttribute(gemm_kernel, cudaFuncAttributeMaxDynamicSharedMemorySize, SMEM_BYTES);

    prep_kernel<<<X_BLOCKS + W_BLOCKS, 128>>>(x, wpack, scale, zero);
    gemm_kernel<<<M_TILES * N_TILES, 256, SMEM_BYTES>>>(out);
}

// round 12
// speedup vs baseline: 1.1484x; 1.1484x over previous
#include <cuda_runtime.h>
#include <cuda_fp16.h>
#include <cstdint>

// ---------------- problem constants ----------------
static constexpr int TOKENS = 4096;
static constexpr int IN_F   = 4096;
static constexpr int OUT_F  = 11008;

static constexpr int BM = 128;
static constexpr int BN = 128;
static constexpr int BK = 64;          // 64 fp16 = 128 bytes per row (SW128 atom row)
static constexpr int STAGES = 3;

static constexpr int M_TILES = TOKENS / BM;   // 32
static constexpr int N_TILES = OUT_F / BN;    // 86
static constexpr int K_TILES = IN_F / BK;     // 64

static constexpr int TILE_BYTES = 128 * BK * 2;     // 16384 (A tile == B tile)
static constexpr int STAGE_BYTES = 2 * TILE_BYTES;  // 32768
static constexpr int SMEM_BYTES = STAGES * STAGE_BYTES; // 98304

static constexpr int X_BLOCKS = M_TILES * K_TILES;  // 2048
static constexpr int W_BLOCKS = N_TILES * K_TILES;  // 5504

// ---------------- device scratch (no cudaMalloc allowed) ----------------
__device__ __align__(1024) uint8_t g_xbuf[(size_t)M_TILES * K_TILES * TILE_BYTES]; // 32 MB fp16 tiles, SW128
__device__ __align__(1024) uint8_t g_wbuf[(size_t)N_TILES * K_TILES * TILE_BYTES]; // 88 MB fp16 tiles, SW128

// ---------------- helpers ----------------
__device__ __forceinline__ uint32_t smem_u32(const void* p) {
    uint32_t a;
    asm("{ .reg .u64 t; cvta.to.shared.u64 t, %1; cvt.u32.u64 %0, t; }" : "=r"(a) : "l"(p));
    return a;
}
__device__ __forceinline__ uint32_t h2u(__half2 h) { uint32_t u; __builtin_memcpy(&u, &h, 4); return u; }
__device__ __forceinline__ uint32_t swz(uint32_t off) { return off ^ ((off >> 3) & 0x70); }

__device__ __forceinline__ void cpasync16(uint32_t dst, const void* src) {
    asm volatile("cp.async.cg.shared.global [%0], [%1], 16;" :: "r"(dst), "l"(src));
}
__device__ __forceinline__ void cp_commit() { asm volatile("cp.async.commit_group;" ::: "memory"); }
__device__ __forceinline__ void cp_wait1()  { asm volatile("cp.async.wait_group 1;" ::: "memory"); }

__device__ __forceinline__ void ldsm4(uint32_t* r, uint32_t addr) {
    asm volatile("ldmatrix.sync.aligned.m8n8.x4.shared.b16 {%0,%1,%2,%3}, [%4];"
                 : "=r"(r[0]), "=r"(r[1]), "=r"(r[2]), "=r"(r[3]) : "r"(addr) : "memory");
}
__device__ __forceinline__ void mma16816(float* c, const uint32_t* a, const uint32_t* b) {
    asm volatile(
        "mma.sync.aligned.m16n8k16.row.col.f32.f16.f16.f32 "
        "{%0,%1,%2,%3}, {%4,%5,%6,%7}, {%8,%9}, {%0,%1,%2,%3};"
        : "+f"(c[0]), "+f"(c[1]), "+f"(c[2]), "+f"(c[3])
        : "r"(a[0]), "r"(a[1]), "r"(a[2]), "r"(a[3]), "r"(b[0]), "r"(b[1]));
}

// ---------------- merged prep kernel ----------------
__global__ void prep_kernel(const float* __restrict__ x,
                            const int* __restrict__ wp,
                            const float* __restrict__ scale,
                            const float* __restrict__ zero) {
    const int blk = blockIdx.x;
    const int r = threadIdx.x; // 0..127 = row within tile
    if (blk < X_BLOCKS) {
        const int mt = blk / K_TILES;
        const int kt = blk % K_TILES;
        const float4* src = (const float4*)(x + (size_t)(mt * BM + r) * IN_F + kt * BK);
        uint8_t* dst = g_xbuf + (size_t)blk * TILE_BYTES;
#pragma unroll
        for (int g = 0; g < 8; g++) {
            float4 a = src[2 * g];
            float4 b = src[2 * g + 1];
            uint4 v;
            v.x = h2u(__floats2half2_rn(a.x, a.y));
            v.y = h2u(__floats2half2_rn(a.z, a.w));
            v.z = h2u(__floats2half2_rn(b.x, b.y));
            v.w = h2u(__floats2half2_rn(b.z, b.w));
            uint32_t off = (uint32_t)(r * 128 + g * 16);
            *(uint4*)(dst + swz(off)) = v;
        }
    } else {
        const int wblk = blk - X_BLOCKS;
        const int nt = wblk / K_TILES;
        const int kt = wblk % K_TILES;
        const int row = nt * BN + r;
        const float s = scale[row];
        const float b = -zero[row] * s;
        const uint4* src = (const uint4*)(wp + (size_t)row * (IN_F / 2) + kt * (BK / 2)); // 32 ints
        uint8_t* dst = g_wbuf + (size_t)wblk * TILE_BYTES;
#pragma unroll
        for (int j = 0; j < 8; j++) {
            uint4 q = src[j];
            uint32_t e[4] = {q.x, q.y, q.z, q.w};
            uint32_t h[4];
#pragma unroll
            for (int t = 0; t < 4; t++) {
                float v0 = fmaf((float)(e[t] & 15u), s, b);          // even k
                float v1 = fmaf((float)((e[t] >> 4) & 15u), s, b);   // odd k
                h[t] = h2u(__floats2half2_rn(v0, v1));
            }
            uint4 v = make_uint4(h[0], h[1], h[2], h[3]);
            uint32_t off = (uint32_t)(r * 128 + j * 16);
            *(uint4*)(dst + swz(off)) = v;
        }
    }
}

// ---------------- main GEMM: 4 warps (2x2), warp tile 64x64, 3-stage cp.async ----------------
// 128 threads, 2 CTAs/SM -> 255-reg budget (no spills), smem traffic 2/3 of 8-warp layout.
__global__ void __launch_bounds__(128, 2) gemm_kernel(float* __restrict__ out) {
    extern __shared__ __align__(1024) uint8_t sm[];
    uint32_t sb = smem_u32(sm);
    const int tid  = threadIdx.x;
    const int lane = tid & 31;
    const int warp = tid >> 5;         // 0..3
    const int warp_m = warp & 1;
    const int warp_n = warp >> 1;
    const int mt = blockIdx.x % M_TILES;
    const int nt = blockIdx.x / M_TILES;

    const uint8_t* ag = g_xbuf + (size_t)(mt * K_TILES) * TILE_BYTES;
    const uint8_t* bg = g_wbuf + (size_t)(nt * K_TILES) * TILE_BYTES;

    // per-thread cp.async slice: 8x16B from A tile + 8x16B from B tile (128 threads)
    const uint32_t cp_off = (uint32_t)tid * 128;

    // prologue: stages 0 and 1
#pragma unroll
    for (int s = 0; s < 2; s++) {
        uint32_t dA = sb + s * STAGE_BYTES + cp_off;
        uint32_t dB = dA + TILE_BYTES;
        const uint8_t* srcA = ag + (size_t)s * TILE_BYTES + cp_off;
        const uint8_t* srcB = bg + (size_t)s * TILE_BYTES + cp_off;
#pragma unroll
        for (int j = 0; j < 8; j++) {
            cpasync16(dA + j * 16, srcA + j * 16);
            cpasync16(dB + j * 16, srcB + j * 16);
        }
        cp_commit();
    }

    // per-lane ldmatrix address components (SW128: swz(r*128+c) = r*128 + (c ^ ((r&7)<<4)))
    const int a_row = warp_m * 64 + (lane & 15);            // + 16*mt2 (mt2=0..3)
    const uint32_t a_xor = (uint32_t)((a_row & 7) << 4);
    const uint32_t a_cb  = (uint32_t)((lane >> 4) << 4);    // 0 or 16
    const int b_row = warp_n * 64 + (lane & 7) + ((lane >> 4) << 3);  // + 16*bp
    const uint32_t b_xor = (uint32_t)((b_row & 7) << 4);
    const uint32_t b_cb  = (uint32_t)((lane & 8) << 1);     // 0 or 16

    uint32_t aoff[4], boff[4];
#pragma unroll
    for (int i = 0; i < 4; i++) {
        aoff[i] = (uint32_t)(a_row + 16 * i) * 128;
        boff[i] = (uint32_t)(b_row + 16 * i) * 128;
    }

    float acc[4][8][4];
#pragma unroll
    for (int i = 0; i < 4; i++)
#pragma unroll
        for (int j = 0; j < 8; j++)
#pragma unroll
            for (int q = 0; q < 4; q++) acc[i][j][q] = 0.f;

    uint32_t afrag[2][4][4];  // [k16 parity][mt2][regs]
    uint32_t bfrag[2][4];     // [step parity][regs]

#pragma unroll 1
    for (int kt = 0; kt < K_TILES; kt++) {
        cp_wait1();
        __syncthreads();

        // issue stage kt+2
        if (kt + 2 < K_TILES) {
            int s = (kt + 2) % STAGES;
            uint32_t dA = sb + s * STAGE_BYTES + cp_off;
            uint32_t dB = dA + TILE_BYTES;
            const uint8_t* srcA = ag + (size_t)(kt + 2) * TILE_BYTES + cp_off;
            const uint8_t* srcB = bg + (size_t)(kt + 2) * TILE_BYTES + cp_off;
#pragma unroll
            for (int j = 0; j < 8; j++) {
                cpasync16(dA + j * 16, srcA + j * 16);
                cpasync16(dB + j * 16, srcB + j * 16);
            }
        }
        cp_commit();

        // compute stage kt
        uint32_t sA = sb + (kt % STAGES) * STAGE_BYTES;
        uint32_t sB = sA + TILE_BYTES;

        // prime: A for k16=0 (4 ldsm), B for step 0
        {
            uint32_t kc0 = a_cb ^ a_xor;
#pragma unroll
            for (int i = 0; i < 4; i++) ldsm4(afrag[0][i], sA + aoff[i] + kc0);
            ldsm4(bfrag[0], sB + boff[0] + (b_cb ^ b_xor));
        }

#pragma unroll
        for (int step = 0; step < 16; step++) {
            const int k16 = step >> 2;
            const int bp  = step & 3;
            // prefetch A for k16+1 at start of each k16 group
            if (bp == 0 && k16 < 3) {
                uint32_t kn = ((uint32_t)((k16 + 1) * 32) + a_cb) ^ a_xor;
#pragma unroll
                for (int i = 0; i < 4; i++) ldsm4(afrag[(k16 + 1) & 1][i], sA + aoff[i] + kn);
            }
            // prefetch B for step+1 (distance = 8 mma)
            if (step < 15) {
                const int k16n = (step + 1) >> 2;
                const int bpn  = (step + 1) & 3;
                uint32_t kcn = (uint32_t)(k16n * 32);
                ldsm4(bfrag[(step + 1) & 1], sB + boff[bpn] + ((kcn + b_cb) ^ b_xor));
            }
            const uint32_t* bb = bfrag[step & 1];
#pragma unroll
            for (int i = 0; i < 4; i++) {
                mma16816(acc[i][2 * bp + 0], afrag[k16 & 1][i], bb + 0);
                mma16816(acc[i][2 * bp + 1], afrag[k16 & 1][i], bb + 2);
            }
        }
    }

    // epilogue: plain accumulator stores (scale/zero already folded into W)
    const int m_base = mt * BM + warp_m * 64 + (lane >> 2);
    const int n_base = nt * BN + warp_n * 64 + 2 * (lane & 3);
#pragma unroll
    for (int i = 0; i < 4; i++) {
        int m0 = m_base + 16 * i;
        float* o0 = out + (size_t)m0 * OUT_F + n_base;
        float* o1 = o0 + (size_t)8 * OUT_F;
#pragma unroll
        for (int j = 0; j < 8; j++) {
            // acc[i][j] covers n = n_base + (j>>1)*16 + (j&1)*8
            int nofs = (j >> 1) * 16 + (j & 1) * 8;
            float2 v0, v1;
            v0.x = acc[i][j][0];
            v0.y = acc[i][j][1];
            v1.x = acc[i][j][2];
            v1.y = acc[i][j][3];
            *(float2*)(o0 + nofs) = v0;
            *(float2*)(o1 + nofs) = v1;
        }
    }
}

// ---------------- launch ----------------
extern "C" void kernel_launch(void* const* d_in, const int* in_sizes, int n_in,
                              void* d_out, int out_size) {
    const float* x     = (const float*)d_in[0];
    const int*   wpack = (const int*)d_in[1];   // uint8 promoted to int32 by harness
    const float* scale = (const float*)d_in[2];
    const float* zero  = (const float*)d_in[3];
    float*       out   = (float*)d_out;

    cudaFuncSetAttribute(gemm_kernel, cudaFuncAttributeMaxDynamicSharedMemorySize, SMEM_BYTES);

    prep_kernel<<<X_BLOCKS + W_BLOCKS, 128>>>(x, wpack, scale, zero);
    gemm_kernel<<<M_TILES * N_TILES, 128, SMEM_BYTES>>>(out);
}

// round 13
// speedup vs baseline: 1.5197x; 1.3233x over previous
#include <cuda_runtime.h>
#include <cuda_fp16.h>
#include <cstdint>

// ---------------- problem constants ----------------
static constexpr int TOKENS = 4096;
static constexpr int IN_F   = 4096;
static constexpr int OUT_F  = 11008;

static constexpr int BM = 128;
static constexpr int BN = 128;
static constexpr int BK = 64;          // 64 fp16 = 128 bytes per row (SW128 atom row)
static constexpr int STAGES = 3;

static constexpr int M_TILES = TOKENS / BM;   // 32
static constexpr int N_TILES = OUT_F / BN;    // 86
static constexpr int K_TILES = IN_F / BK;     // 64

static constexpr int TILE_BYTES = 128 * BK * 2;     // 16384 (A tile == B tile)
static constexpr int STAGE_BYTES = 2 * TILE_BYTES;  // 32768
static constexpr int SMEM_BYTES = STAGES * STAGE_BYTES; // 98304

static constexpr int X_BLOCKS = M_TILES * K_TILES;  // 2048
static constexpr int W_BLOCKS = N_TILES * K_TILES;  // 5504

// ---------------- device scratch (no cudaMalloc allowed) ----------------
__device__ __align__(1024) uint8_t g_xbuf[(size_t)M_TILES * K_TILES * TILE_BYTES]; // 32 MB fp16 tiles, SW128
__device__ __align__(1024) uint8_t g_wbuf[(size_t)N_TILES * K_TILES * TILE_BYTES]; // 88 MB fp16 tiles, SW128

// ---------------- helpers ----------------
__device__ __forceinline__ uint32_t smem_u32(const void* p) {
    uint32_t a;
    asm("{ .reg .u64 t; cvta.to.shared.u64 t, %1; cvt.u32.u64 %0, t; }" : "=r"(a) : "l"(p));
    return a;
}
__device__ __forceinline__ uint32_t h2u(__half2 h) { uint32_t u; __builtin_memcpy(&u, &h, 4); return u; }
__device__ __forceinline__ uint32_t swz(uint32_t off) { return off ^ ((off >> 3) & 0x70); }

__device__ __forceinline__ void cpasync16(uint32_t dst, const void* src) {
    asm volatile("cp.async.cg.shared.global [%0], [%1], 16;" :: "r"(dst), "l"(src));
}
__device__ __forceinline__ void cp_commit() { asm volatile("cp.async.commit_group;" ::: "memory"); }
__device__ __forceinline__ void cp_wait1()  { asm volatile("cp.async.wait_group 1;" ::: "memory"); }

__device__ __forceinline__ void ldsm4(uint32_t* r, uint32_t addr) {
    asm volatile("ldmatrix.sync.aligned.m8n8.x4.shared.b16 {%0,%1,%2,%3}, [%4];"
                 : "=r"(r[0]), "=r"(r[1]), "=r"(r[2]), "=r"(r[3]) : "r"(addr) : "memory");
}
__device__ __forceinline__ void mma16816(float* c, const uint32_t* a, const uint32_t* b) {
    asm volatile(
        "mma.sync.aligned.m16n8k16.row.col.f32.f16.f16.f32 "
        "{%0,%1,%2,%3}, {%4,%5,%6,%7}, {%8,%9}, {%0,%1,%2,%3};"
        : "+f"(c[0]), "+f"(c[1]), "+f"(c[2]), "+f"(c[3])
        : "r"(a[0]), "r"(a[1]), "r"(a[2]), "r"(a[3]), "r"(b[0]), "r"(b[1]));
}

// ---------------- merged prep kernel ----------------
__global__ void prep_kernel(const float* __restrict__ x,
                            const int* __restrict__ wp,
                            const float* __restrict__ scale,
                            const float* __restrict__ zero) {
    const int blk = blockIdx.x;
    const int r = threadIdx.x; // 0..127 = row within tile
    if (blk < X_BLOCKS) {
        const int mt = blk / K_TILES;
        const int kt = blk % K_TILES;
        const float4* src = (const float4*)(x + (size_t)(mt * BM + r) * IN_F + kt * BK);
        uint8_t* dst = g_xbuf + (size_t)blk * TILE_BYTES;
#pragma unroll
        for (int g = 0; g < 8; g++) {
            float4 a = src[2 * g];
            float4 b = src[2 * g + 1];
            uint4 v;
            v.x = h2u(__floats2half2_rn(a.x, a.y));
            v.y = h2u(__floats2half2_rn(a.z, a.w));
            v.z = h2u(__floats2half2_rn(b.x, b.y));
            v.w = h2u(__floats2half2_rn(b.z, b.w));
            uint32_t off = (uint32_t)(r * 128 + g * 16);
            *(uint4*)(dst + swz(off)) = v;
        }
    } else {
        const int wblk = blk - X_BLOCKS;
        const int nt = wblk / K_TILES;
        const int kt = wblk % K_TILES;
        const int row = nt * BN + r;
        const float s = scale[row];
        const float b = -zero[row] * s;
        const uint4* src = (const uint4*)(wp + (size_t)row * (IN_F / 2) + kt * (BK / 2)); // 32 ints
        uint8_t* dst = g_wbuf + (size_t)wblk * TILE_BYTES;
#pragma unroll
        for (int j = 0; j < 8; j++) {
            uint4 q = src[j];
            uint32_t e[4] = {q.x, q.y, q.z, q.w};
            uint32_t h[4];
#pragma unroll
            for (int t = 0; t < 4; t++) {
                float v0 = fmaf((float)(e[t] & 15u), s, b);          // even k
                float v1 = fmaf((float)((e[t] >> 4) & 15u), s, b);   // odd k
                h[t] = h2u(__floats2half2_rn(v0, v1));
            }
            uint4 v = make_uint4(h[0], h[1], h[2], h[3]);
            uint32_t off = (uint32_t)(r * 128 + j * 16);
            *(uint4*)(dst + swz(off)) = v;
        }
    }
}

// ---------------- main GEMM: mma.sync + cp.async 3-stage, B double-buffered per k16 ----------------
// 256 threads = 8 warps in a 4(M) x 2(N) grid; warp tile 32x64; 2 CTAs/SM.
__global__ void __launch_bounds__(256, 2) gemm_kernel(float* __restrict__ out) {
    extern __shared__ __align__(1024) uint8_t sm[];
    uint32_t sb = smem_u32(sm);
    const int tid  = threadIdx.x;
    const int lane = tid & 31;
    const int warp = tid >> 5;
    const int warp_m = warp & 3;
    const int warp_n = warp >> 2;
    const int mt = blockIdx.x % M_TILES;
    const int nt = blockIdx.x / M_TILES;

    const uint8_t* ag = g_xbuf + (size_t)(mt * K_TILES) * TILE_BYTES;
    const uint8_t* bg = g_wbuf + (size_t)(nt * K_TILES) * TILE_BYTES;

    const uint32_t cp_off = (uint32_t)tid * 64;

    // prologue: stages 0 and 1
#pragma unroll
    for (int s = 0; s < 2; s++) {
        uint32_t dA = sb + s * STAGE_BYTES + cp_off;
        uint32_t dB = dA + TILE_BYTES;
        const uint8_t* srcA = ag + (size_t)s * TILE_BYTES + cp_off;
        const uint8_t* srcB = bg + (size_t)s * TILE_BYTES + cp_off;
#pragma unroll
        for (int j = 0; j < 4; j++) {
            cpasync16(dA + j * 16, srcA + j * 16);
            cpasync16(dB + j * 16, srcB + j * 16);
        }
        cp_commit();
    }

    // per-lane ldmatrix address components (SW128: swz(r*128+c) = r*128 + (c ^ ((r&7)<<4)))
    const int a_row = warp_m * 32 + (lane & 15);          // + 16*mtile
    const uint32_t a_xor = (uint32_t)((a_row & 7) << 4);
    const uint32_t a_cb  = (uint32_t)((lane >> 4) << 4);  // 0 or 16
    const int b_row = warp_n * 64 + (lane & 7) + ((lane >> 4) << 3);  // + 16*p
    const uint32_t b_xor = (uint32_t)((b_row & 7) << 4);
    const uint32_t b_cb  = (uint32_t)((lane & 8) << 1);   // 0 or 16

    const uint32_t aoff0 = (uint32_t)(a_row +  0) * 128;
    const uint32_t aoff1 = (uint32_t)(a_row + 16) * 128;
    uint32_t boff[4];
#pragma unroll
    for (int p = 0; p < 4; p++) boff[p] = (uint32_t)(b_row + 16 * p) * 128;

    float acc[2][8][4];
#pragma unroll
    for (int i = 0; i < 2; i++)
#pragma unroll
        for (int j = 0; j < 8; j++)
#pragma unroll
            for (int q = 0; q < 4; q++) acc[i][j][q] = 0.f;

    uint32_t bfr[2][16];   // [k16 parity][4 groups x 4 regs]
    uint32_t afr[2][4];    // current k16 A, 2 mtiles

#pragma unroll 1
    for (int kt = 0; kt < K_TILES; kt++) {
        cp_wait1();
        __syncthreads();

        // issue stage kt+2
        if (kt + 2 < K_TILES) {
            int s = (kt + 2) % STAGES;
            uint32_t dA = sb + s * STAGE_BYTES + cp_off;
            uint32_t dB = dA + TILE_BYTES;
            const uint8_t* srcA = ag + (size_t)(kt + 2) * TILE_BYTES + cp_off;
            const uint8_t* srcB = bg + (size_t)(kt + 2) * TILE_BYTES + cp_off;
#pragma unroll
            for (int j = 0; j < 4; j++) {
                cpasync16(dA + j * 16, srcA + j * 16);
                cpasync16(dB + j * 16, srcB + j * 16);
            }
        }
        cp_commit();

        // compute stage kt
        uint32_t sA = sb + (kt % STAGES) * STAGE_BYTES;
        uint32_t sB = sA + TILE_BYTES;

        // prime B for k16=0
        {
            uint32_t kx = b_cb ^ b_xor;
#pragma unroll
            for (int p = 0; p < 4; p++) ldsm4(&bfr[0][4 * p], sB + boff[p] + kx);
        }

#pragma unroll
        for (int k16 = 0; k16 < 4; k16++) {
            // A for this k16 (short exposure, covered by B ldsm + prior mma)
            uint32_t ka = ((uint32_t)(k16 * 32) + a_cb) ^ a_xor;
            ldsm4(afr[0], sA + aoff0 + ka);
            ldsm4(afr[1], sA + aoff1 + ka);
            // prefetch all 4 B groups for k16+1 (use distance = 16 mma)
            if (k16 < 3) {
                uint32_t kx = ((uint32_t)((k16 + 1) * 32) + b_cb) ^ b_xor;
#pragma unroll
                for (int p = 0; p < 4; p++) ldsm4(&bfr[(k16 + 1) & 1][4 * p], sB + boff[p] + kx);
            }
            // 16 mma on current buffers
#pragma unroll
            for (int p = 0; p < 4; p++) {
                const uint32_t* bb = &bfr[k16 & 1][4 * p];
                mma16816(acc[0][2 * p + 0], afr[0], bb + 0);
                mma16816(acc[0][2 * p + 1], afr[0], bb + 2);
                mma16816(acc[1][2 * p + 0], afr[1], bb + 0);
                mma16816(acc[1][2 * p + 1], afr[1], bb + 2);
            }
        }
    }

    // epilogue: plain accumulator stores (scale/zero already folded into W)
    const int m_lo = mt * BM + warp_m * 32 + (lane >> 2);
    const int n_lo = nt * BN + warp_n * 64 + 2 * (lane & 3);
#pragma unroll
    for (int mtile = 0; mtile < 2; mtile++) {
        int m0 = m_lo + 16 * mtile;
        float* o0 = out + (size_t)m0 * OUT_F + n_lo;
        float* o1 = o0 + (size_t)8 * OUT_F;
#pragma unroll
        for (int p = 0; p < 8; p++) {
            float2 v0, v1;
            v0.x = acc[mtile][p][0];
            v0.y = acc[mtile][p][1];
            v1.x = acc[mtile][p][2];
            v1.y = acc[mtile][p][3];
            *(float2*)(o0 + 8 * p) = v0;
            *(float2*)(o1 + 8 * p) = v1;
        }
    }
}

// ---------------- launch ----------------
extern "C" void kernel_launch(void* const* d_in, const int* in_sizes, int n_in,
                              void* d_out, int out_size) {
    const float* x     = (const float*)d_in[0];
    const int*   wpack = (const int*)d_in[1];   // uint8 promoted to int32 by harness
    const float* scale = (const float*)d_in[2];
    const float* zero  = (const float*)d_in[3];
    float*       out   = (float*)d_out;

    cudaFuncSetAttribute(gemm_kernel, cudaFuncAttributeMaxDynamicSharedMemorySize, SMEM_BYTES);

    prep_kernel<<<X_BLOCKS + W_BLOCKS, 128>>>(x, wpack, scale, zero);
    gemm_kernel<<<M_TILES * N_TILES, 256, SMEM_BYTES>>>(out);
}